// round 15
// baseline (speedup 1.0000x reference)
#include <cuda_runtime.h>
#include <math.h>
#include <stdint.h>

#define BB 128
#define NN 512
#define FT 64
#define DD 64
#define TOPK 20
#define M_ROWS (BB*NN)          // 65536
#define NEG_SLOPE 0.2f
#define BN_EPS 1e-5f
#define BP 68                   // B smem pitch (bank = 4g+t, conflict-free)

// ---- scratch (device globals; no allocation allowed) ----
__device__ int   g_topk[NN*TOPK];
__device__ float g_rst[M_ROWS*DD];      // 16 MB staging (coalesced)
__device__ float g_psum[BB*DD];
__device__ float g_psq[BB*DD];
__device__ float g_mu[DD];
__device__ float g_scale[DD];
__device__ unsigned int g_ctr_topk = 0;
__device__ unsigned int g_ctr  = 0;
__device__ unsigned int g_ctr2 = 0;
__device__ unsigned int g_done = 0;

__device__ __forceinline__ uint32_t f2tf32(float x) {
    uint32_t r;
    asm("cvt.rna.tf32.f32 %0, %1;" : "=r"(r) : "f"(x));
    return r;
}

#define MMA_TF32(ac, a0,a1,a2,a3, b0,b1) \
    asm volatile("mma.sync.aligned.m16n8k8.row.col.f32.tf32.tf32.f32 " \
        "{%0,%1,%2,%3}, {%4,%5,%6,%7}, {%8,%9}, {%0,%1,%2,%3};" \
        : "+f"((ac)[0]), "+f"((ac)[1]), "+f"((ac)[2]), "+f"((ac)[3]) \
        : "r"(a0), "r"(a1), "r"(a2), "r"(a3), "r"(b0), "r"(b1))

// ============================================================
// THE mega kernel: one launch, 128 blocks x 1024 threads.
//  phase 0: stage emb (rotation layout) -> zs; local norms,
//           tsrc/tdst; 4 cos rows per block; top-20 selection;
//           publish g_topk + arrive on topk counter.
//  phase 1: load data[b] -> zs (XOR swizzle), fc_w hi/lo split.
//  phase 2: in-block split-tf32 MMA z = data@fc_w^T + b; scores.
//  (wait for all blocks' topk)
//  phase 3: edge softmax; pack (alpha, swizzled base) pairs.
//  phase 4: gather/aggregate (LDS.128 alpha pairs, base^lane
//           indexing) + BN partials (rst -> g_rst).
//  phase 5: grid-sync, BN stats, normalize+relu+out-projection.
// dyn smem: zs[32768] | rg2[20480]  (213 KB)
// data swizzle: element d of row r at  d ^ ((r&7)*4).
// emb rotation: element d of row r at  (d + r) & 63.
// ============================================================
__global__ void __launch_bounds__(1024, 1)
k_mega(const float* __restrict__ data, const float* __restrict__ fc_w,
       const float* __restrict__ fc_b, const float* __restrict__ attn_w,
       const float* __restrict__ emb, const float* __restrict__ attn_b,
       const float* __restrict__ bn_gamma, const float* __restrict__ bn_beta,
       const float* __restrict__ out_w, const float* __restrict__ out_b,
       float* __restrict__ out) {
    extern __shared__ float smem[];
    float*  zs  = smem;                               // 32768 floats
    float*  rg2 = smem + NN*DD;                       // 20480 floats
    // phase-0 overlays
    float*  cosv  = rg2;                              // 2048 (4 x 512)
    float*  snorm = rg2 + 2048;                       // 512
    float*  s_ts  = rg2 + 8704;                       // 512 (lives into phase 2)
    float*  s_td  = rg2 + 9216;                       // 512
    // phase-1/2 overlays
    float*  sBh = rg2;                                // 64*68 = 4352
    float*  sBl = rg2 + 64*BP;                        // 4352 (ends 8704)
    // phase-3/4 overlays
    float2* apack = (float2*)rg2;                     // 10240 float2
    float*  wsum = rg2;                               // [32][64]
    float*  wsq  = rg2 + 2048;                        // [32][64]
    __shared__ float s_ssrc[NN];
    __shared__ float s_sdst[NN];
    __shared__ float s_aw[2*DD];                      // emb halves of a_src/a_dst
    __shared__ unsigned int s_last;

    int tid = threadIdx.x;                            // 1024
    int b = blockIdx.x;
    int lane = tid & 31, w = tid >> 5;                // w: 0..31
    int g = lane >> 2, t = lane & 3;

    // ---- phase 0a: stage emb (rotation layout) + attn_w emb-halves ----
    {
        const float4* esrc = reinterpret_cast<const float4*>(emb);
        #pragma unroll
        for (int i = 0; i < 8; i++) {
            int i4 = tid + i*1024;                    // 8192 float4 total
            float4 v = esrc[i4];
            int r = i4 >> 4;
            int c = (i4 & 15) * 4;
            zs[r*64 + ((c+0+r)&63)] = v.x;
            zs[r*64 + ((c+1+r)&63)] = v.y;
            zs[r*64 + ((c+2+r)&63)] = v.z;
            zs[r*64 + ((c+3+r)&63)] = v.w;
        }
        if (tid < 128) s_aw[tid] = attn_w[(tid < 64) ? (64 + tid) : (128 + tid)];
    }
    __syncthreads();

    // ---- phase 0b: norms (tid<512) and tsrc/tdst (tid>=512) ----
    if (tid < NN) {
        int r = tid;
        float s2 = 0.f;
        #pragma unroll 16
        for (int d = 0; d < 64; d++) { float v = zs[r*64 + ((d+r)&63)]; s2 += v*v; }
        snorm[r] = sqrtf(s2);
    } else {
        int r = tid - NN;
        float ts = 0.f, td = 0.f;
        #pragma unroll 16
        for (int d = 0; d < 64; d++) {
            float v = zs[r*64 + ((d+r)&63)];
            ts += v * s_aw[d];
            td += v * s_aw[64 + d];
        }
        s_ts[r] = ts;
        s_td[r] = td;
    }
    __syncthreads();

    // ---- phase 0c: 4 cos rows (n0..n0+3); thread: col m, 2 rows ----
    int n0 = b * 4;
    {
        int m  = tid & 511;
        int rl = tid >> 9;                            // 0 or 1
        int na = n0 + rl, nb = n0 + rl + 2;
        float d0 = 0.f, d1 = 0.f;
        #pragma unroll 8
        for (int d = 0; d < 64; d++) {
            float vm = zs[m*64 + ((d+m)&63)];         // conflict-free stream
            d0 += zs[na*64 + ((d+na)&63)] * vm;       // broadcast
            d1 += zs[nb*64 + ((d+nb)&63)] * vm;       // broadcast
        }
        float nm = snorm[m];
        cosv[rl*512 + m]     = d0 / (snorm[na] * nm);
        cosv[(rl+2)*512 + m] = d1 / (snorm[nb] * nm);
    }
    __syncthreads();

    // ---- phase 0d: top-20 selection, warps 0..3 -> rows n0..n0+3 ----
    if (w < 4) {
        float sl[16];
        #pragma unroll
        for (int j = 0; j < 16; j++) sl[j] = cosv[w*512 + j*32 + lane];
        for (int k = 0; k < TOPK; k++) {
            float bv = sl[0]; int bi = lane;
            #pragma unroll
            for (int j = 1; j < 16; j++) {
                int idx = j*32 + lane;
                if (sl[j] > bv) { bv = sl[j]; bi = idx; }
            }
            #pragma unroll
            for (int o = 16; o > 0; o >>= 1) {
                float ov = __shfl_xor_sync(0xFFFFFFFFu, bv, o);
                int   oi = __shfl_xor_sync(0xFFFFFFFFu, bi, o);
                if (ov > bv || (ov == bv && oi < bi)) { bv = ov; bi = oi; }
            }
            if (lane == 0) g_topk[(n0 + w)*TOPK + k] = bi;
            if ((bi & 31) == lane) {
                int j = bi >> 5;
                #pragma unroll
                for (int jj = 0; jj < 16; jj++) if (jj == j) sl[jj] = -INFINITY;
            }
        }
    }
    __threadfence();                                  // topk stores visible
    __syncthreads();
    if (tid == 0) atomicAdd(&g_ctr_topk, 1u);         // publish early

    // ---- phase 1: data[b] -> zs (XOR swizzle) + fc_w hi/lo split ----
    {
        const float4* dsrc = reinterpret_cast<const float4*>(data + (size_t)b * NN * DD);
        float4* zs4 = reinterpret_cast<float4*>(zs);
        #pragma unroll
        for (int i = 0; i < 8; i++) {
            int idx = tid + i*1024;
            int row = idx >> 4, c4 = idx & 15;
            zs4[row*16 + (c4 ^ (row & 7))] = dsrc[idx];
        }
        #pragma unroll
        for (int i = 0; i < 4; i++) {
            int idx = tid + i*1024;
            int r = idx >> 6, c = idx & 63;
            float v = fc_w[idx];
            uint32_t hb = f2tf32(v);
            float hf = __uint_as_float(hb);
            sBh[r*BP + c] = hf;
            sBl[r*BP + c] = __uint_as_float(f2tf32(v - hf));
        }
    }
    __syncthreads();

    // ---- phase 2: in-block split-tf32 MMA, warp w -> rows w*16.. ----
    int r0 = w*16 + g;                                // and r0+8
    int sw = (r0 & 7) * 4;
    {
        float acc[8][4] = {};
        #pragma unroll
        for (int kk = 0; kk < 8; kk++) {
            int c0a = kk*8 + t, c1a = c0a + 4;
            float a0f = zs[r0*64     + (c0a ^ sw)];
            float a1f = zs[(r0+8)*64 + (c0a ^ sw)];
            float a2f = zs[r0*64     + (c1a ^ sw)];
            float a3f = zs[(r0+8)*64 + (c1a ^ sw)];
            uint32_t ah0 = f2tf32(a0f), ah1 = f2tf32(a1f);
            uint32_t ah2 = f2tf32(a2f), ah3 = f2tf32(a3f);
            uint32_t al0 = f2tf32(a0f - __uint_as_float(ah0));
            uint32_t al1 = f2tf32(a1f - __uint_as_float(ah1));
            uint32_t al2 = f2tf32(a2f - __uint_as_float(ah2));
            uint32_t al3 = f2tf32(a3f - __uint_as_float(ah3));
            #pragma unroll
            for (int j = 0; j < 8; j++) {
                int bn = j*8 + g;
                uint32_t bh0 = __float_as_uint(sBh[bn*BP + c0a]);
                uint32_t bh1 = __float_as_uint(sBh[bn*BP + c1a]);
                uint32_t bl0 = __float_as_uint(sBl[bn*BP + c0a]);
                uint32_t bl1 = __float_as_uint(sBl[bn*BP + c1a]);
                MMA_TF32(acc[j], ah0, ah1, ah2, ah3, bh0, bh1);   // hi*hi
                MMA_TF32(acc[j], al0, al1, al2, al3, bh0, bh1);   // lo*hi
                MMA_TF32(acc[j], ah0, ah1, ah2, ah3, bl0, bl1);   // hi*lo
            }
        }

        // epilogue: bias, z -> zs (swizzled, own rows only), fused scores
        float ds0 = 0.f, dd0 = 0.f, ds1 = 0.f, dd1 = 0.f;
        #pragma unroll
        for (int j = 0; j < 8; j++) {
            int nn0 = j*8 + 2*t;
            float b0 = __ldg(&fc_b[nn0]), b1 = __ldg(&fc_b[nn0+1]);
            float z00 = acc[j][0] + b0, z01 = acc[j][1] + b1;
            float z10 = acc[j][2] + b0, z11 = acc[j][3] + b1;
            float2 v0; v0.x = z00; v0.y = z01;
            float2 v1; v1.x = z10; v1.y = z11;
            *reinterpret_cast<float2*>(&zs[r0*64     + (nn0 ^ sw)]) = v0;
            *reinterpret_cast<float2*>(&zs[(r0+8)*64 + (nn0 ^ sw)]) = v1;
            float as0 = __ldg(&attn_w[nn0]),     as1 = __ldg(&attn_w[nn0+1]);
            float ad0 = __ldg(&attn_w[128+nn0]), ad1 = __ldg(&attn_w[128+nn0+1]);
            ds0 += z00*as0 + z01*as1;  dd0 += z00*ad0 + z01*ad1;
            ds1 += z10*as0 + z11*as1;  dd1 += z10*ad0 + z11*ad1;
        }
        #pragma unroll
        for (int o = 2; o > 0; o >>= 1) {
            ds0 += __shfl_down_sync(0xFFFFFFFFu, ds0, o, 4);
            dd0 += __shfl_down_sync(0xFFFFFFFFu, dd0, o, 4);
            ds1 += __shfl_down_sync(0xFFFFFFFFu, ds1, o, 4);
            dd1 += __shfl_down_sync(0xFFFFFFFFu, dd1, o, 4);
        }
        if (t == 0) {
            s_ssrc[r0]   = ds0 + s_ts[r0];
            s_sdst[r0]   = dd0 + s_td[r0];
            s_ssrc[r0+8] = ds1 + s_ts[r0+8];
            s_sdst[r0+8] = dd1 + s_td[r0+8];
        }
    }
    __syncthreads();        // z + scores complete; rg2 free for apack

    // ---- wait: all blocks' topk published ----
    if (tid == 0) {
        while (atomicAdd(&g_ctr_topk, 0u) < BB) { }
    }
    __syncthreads();
    __threadfence();        // acquire g_topk

    // ---- phase 3: alphas; pack (alpha, swizzled base) pairs ----
    if (tid < NN) {
        int n = tid;
        float sd = s_sdst[n] + __ldg(attn_b);
        float e[TOPK]; int sb[TOPK];
        float mx = -INFINITY;
        #pragma unroll
        for (int tt = 0; tt < TOPK; tt++) {
            int i = n + tt*NN;
            int s = g_topk[(i/TOPK)*TOPK + (i % TOPK)];   // reference's edge wiring
            sb[tt] = s*64 + ((s & 7) << 2);               // precomputed swizzled base
            float x = s_ssrc[s] + sd;
            x = x > 0.f ? x : NEG_SLOPE * x;              // leaky relu
            e[tt] = x;
            mx = fmaxf(mx, x);
        }
        float den = 0.f;
        #pragma unroll
        for (int tt = 0; tt < TOPK; tt++) { float p = expf(e[tt] - mx); e[tt] = p; den += p; }
        float inv = 1.0f / den;
        float4* ap4 = reinterpret_cast<float4*>(apack) + n*(TOPK/2);
        #pragma unroll
        for (int u = 0; u < TOPK/2; u++) {
            float4 pk;
            pk.x = e[2*u]   * inv; pk.y = __int_as_float(sb[2*u]);
            pk.z = e[2*u+1] * inv; pk.w = __int_as_float(sb[2*u+1]);
            ap4[u] = pk;
        }
    }
    __syncthreads();

    // ---- phase 4: gather/aggregate; warp w -> rows w*16..w*16+15 ----
    float ps0 = 0.f, pq0 = 0.f, ps1 = 0.f, pq1 = 0.f;
    int nbase = w * 16;
    #pragma unroll
    for (int rr = 0; rr < 16; rr++) {
        int n = nbase + rr;
        float h0 = 0.f, h1 = 0.f;
        const float4* ap4 = reinterpret_cast<const float4*>(apack) + n*(TOPK/2);
        #pragma unroll
        for (int u = 0; u < TOPK/2; u++) {
            float4 pk = ap4[u];                 // LDS.128 broadcast: 2 edges
            int i0 = __float_as_int(pk.y) ^ lane;   // base ^ lane == s*64 + (lane^swz)
            h0 = fmaf(pk.x, zs[i0],      h0);
            h1 = fmaf(pk.x, zs[i0 + 32], h1);
            int i1 = __float_as_int(pk.w) ^ lane;
            h0 = fmaf(pk.z, zs[i1],      h0);
            h1 = fmaf(pk.z, zs[i1 + 32], h1);
        }
        float e0 = emb[n*64 + lane];
        float e1 = emb[n*64 + 32 + lane];
        float v0 = h0 * e0, v1 = h1 * e1;
        size_t row = (size_t)b*NN + n;
        g_rst[row*64 + lane]      = v0;        // coalesced STG
        g_rst[row*64 + 32 + lane] = v1;
        ps0 += v0; pq0 += v0*v0;
        ps1 += v1; pq1 += v1*v1;
    }
    __syncthreads();                           // apack reads done -> reuse region
    wsum[w*64 + lane]    = ps0; wsum[w*64 + lane+32] = ps1;
    wsq [w*64 + lane]    = pq0; wsq [w*64 + lane+32] = pq1;
    __syncthreads();
    if (tid < 64) {
        float S = 0.f, Q = 0.f;
        #pragma unroll
        for (int ww = 0; ww < 32; ww++) { S += wsum[ww*64 + tid]; Q += wsq[ww*64 + tid]; }
        g_psum[b*64 + tid] = S;
        g_psq [b*64 + tid] = Q;
    }
    __threadfence();
    __syncthreads();
    if (tid == 0) s_last = (atomicAdd(&g_ctr, 1u) == BB - 1u) ? 1u : 0u;
    __syncthreads();

    if (s_last) {
        __threadfence();                       // acquire: all blocks' psum visible
        int d = tid & 63, grp = tid >> 6;      // 16 groups x 64 d, 8 batches each
        float s = 0.f, q = 0.f;
        #pragma unroll
        for (int jj = 0; jj < 8; jj++) {
            int j = grp*8 + jj;
            s += g_psum[j*64 + d];
            q += g_psq [j*64 + d];
        }
        __syncthreads();
        wsum[grp*64 + d] = s; wsq[grp*64 + d] = q;
        __syncthreads();
        if (tid < 64) {
            float S = 0.f, Q = 0.f;
            #pragma unroll
            for (int gg = 0; gg < 16; gg++) { S += wsum[gg*64 + tid]; Q += wsq[gg*64 + tid]; }
            float mu  = S / (float)M_ROWS;
            float var = Q / (float)M_ROWS - mu*mu;   // biased, matches jnp.var
            g_mu[tid]    = mu;
            g_scale[tid] = bn_gamma[tid] / sqrtf(var + BN_EPS);
        }
        __threadfence();
        __syncthreads();
        if (tid == 0) atomicExch(&g_done, 1u);
    }

    // grid-wide wait: 128 blocks, 1/SM, all co-resident
    if (tid == 0) {
        while (atomicAdd(&g_done, 0u) == 0u) { }
    }
    __syncthreads();
    __threadfence();

    // ---- phase 5: BN-normalize + relu + out projection ----
    {
        float mu0 = g_mu[lane],       mu1 = g_mu[lane+32];
        float sc0 = g_scale[lane],    sc1 = g_scale[lane+32];
        float bt0 = bn_beta[lane],    bt1 = bn_beta[lane+32];
        float ow0 = out_w[lane],      ow1 = out_w[lane+32];
        float ob  = __ldg(out_b);
        #pragma unroll
        for (int rr = 0; rr < 16; rr++) {
            size_t row = (size_t)b*NN + nbase + rr;
            float v0 = (g_rst[row*64 + lane]      - mu0) * sc0 + bt0;
            float v1 = (g_rst[row*64 + 32 + lane] - mu1) * sc1 + bt1;
            v0 = v0 > 0.f ? v0 : 0.f;
            v1 = v1 > 0.f ? v1 : 0.f;
            float a = v0*ow0 + v1*ow1;
            #pragma unroll
            for (int o = 16; o > 0; o >>= 1) a += __shfl_down_sync(0xFFFFFFFFu, a, o);
            if (lane == 0) out[b*NN + nbase + rr] = a + ob;
        }
    }

    // reset counters for next graph replay (last block to depart)
    __syncthreads();
    if (tid == 0) {
        if (atomicAdd(&g_ctr2, 1u) == BB - 1u) {
            g_ctr = 0; g_ctr2 = 0; g_done = 0; g_ctr_topk = 0;
            __threadfence();
        }
    }
}

extern "C" void kernel_launch(void* const* d_in, const int* in_sizes, int n_in,
                              void* d_out, int out_size) {
    const float* data     = (const float*)d_in[0];
    const float* emb      = (const float*)d_in[1];
    const float* fc_w     = (const float*)d_in[2];
    const float* fc_b     = (const float*)d_in[3];
    const float* attn_w   = (const float*)d_in[4];
    const float* attn_b   = (const float*)d_in[5];
    const float* bn_gamma = (const float*)d_in[6];
    const float* bn_beta  = (const float*)d_in[7];
    const float* out_w    = (const float*)d_in[8];
    const float* out_b    = (const float*)d_in[9];
    float* out = (float*)d_out;

    const int MEGA_SMEM = (NN*DD + 2*NN*TOPK) * 4;   // 212992 bytes
    static int configured = 0;
    if (!configured) {
        cudaFuncSetAttribute(k_mega, cudaFuncAttributeMaxDynamicSharedMemorySize, MEGA_SMEM);
        configured = 1;
    }

    k_mega<<<BB, 1024, MEGA_SMEM>>>(data, fc_w, fc_b, attn_w,
                                    emb, attn_b, bn_gamma, bn_beta,
                                    out_w, out_b, out);
}